// round 2
// baseline (speedup 1.0000x reference)
#include <cuda_runtime.h>

#define B_N   1024
#define C_N   128
#define I_N   16
#define E_N   10
#define NT3   816           // cubic monomials i0<=i1<=i2
#define NT2   136           // quadratic monomials
#define NT    968           // 816 + 136 + 16
#define NCOMP 4             // L=0 scalar + 3 components of L=1

// ---------------- device scratch (static globals; no allocation) ----------------
__device__ int   g_species[B_N];
__device__ int   g_perm[B_N];
__device__ int   g_tri[NT3];
__device__ int   g_pair[NT2];
__device__ float g_U3S[NCOMP][NT3][8];
__device__ float g_U2S[NCOMP][NT2][4];
__device__ float g_U1S[NCOMP][I_N];
// coefficient table: [c][t][e][comp], comp fastest => one float4 per (c,t,e)
__device__ __align__(16) float g_coef[C_N][NT][E_N][NCOMP];  // 19.8 MB

// ---------------- kernel A: species, sort-by-species, U symmetrization ----------
__global__ void prep_kernel(const float* __restrict__ node_attrs,
                            const float* __restrict__ U3_l0,
                            const float* __restrict__ U3_l1,
                            const float* __restrict__ U2_l0,
                            const float* __restrict__ U2_l1,
                            const float* __restrict__ U1_l0,
                            const float* __restrict__ U1_l1) {
    __shared__ int s_hist[E_N];
    __shared__ int s_off[E_N];
    int tid = threadIdx.x;              // 1024 threads, 1 block
    if (tid < E_N) s_hist[tid] = 0;
    __syncthreads();

    // species from one-hot (exact 1.0/0.0)
    const float* na = node_attrs + tid * E_N;
    int e = 0;
#pragma unroll
    for (int j = 0; j < E_N; j++) if (na[j] > 0.5f) e = j;
    g_species[tid] = e;
    atomicAdd(&s_hist[e], 1);
    __syncthreads();
    if (tid == 0) {
        int acc = 0;
        for (int j = 0; j < E_N; j++) { s_off[j] = acc; acc += s_hist[j]; }
    }
    __syncthreads();
    // grouping by species (order within a species is irrelevant: every b's
    // output is computed identically regardless of which thread owns it)
    int pos = atomicAdd(&s_off[e], 1);
    g_perm[pos] = tid;

    // monomial index tables (same enumeration order as the main kernel's loops)
    if (tid < I_N) {
        int a = tid;
        int off = 0;
        for (int ap = 0; ap < a; ap++) off += (I_N - ap) * (I_N - ap + 1) / 2;
        for (int b = a; b < I_N; b++)
            for (int c = b; c < I_N; c++)
                g_tri[off++] = a | (b << 5) | (c << 10);
        int off2 = 0;
        for (int ap = 0; ap < a; ap++) off2 += (I_N - ap);
        for (int b = a; b < I_N; b++)
            g_pair[off2++] = a | (b << 5);
    }
    __syncthreads();

    // symmetrized U3: sum over all 6 index permutations / repetition factor
    for (int item = tid; item < NCOMP * NT3; item += blockDim.x) {
        int comp = item / NT3, t = item % NT3;
        int tr = g_tri[t];
        int a = tr & 31, b = (tr >> 5) & 31, c = (tr >> 10) & 31;
        // a<=b<=c: all equal -> /6 ; exactly two equal -> /2 ; distinct -> /1
        float inv = (a == c) ? (1.f / 6.f) : ((a == b || b == c) ? 0.5f : 1.f);
        int kN; const float* U;
        if (comp == 0) { kN = 5; U = U3_l0; }
        else           { kN = 7; U = U3_l1 + (comp - 1) * (I_N * I_N * I_N * 7); }
        for (int k = 0; k < 8; k++) {
            float s = 0.f;
            if (k < kN) {
                auto at = [&](int i0, int i1, int i2) {
                    return U[((i0 * I_N + i1) * I_N + i2) * kN + k];
                };
                s = at(a,b,c) + at(a,c,b) + at(b,a,c) + at(b,c,a) + at(c,a,b) + at(c,b,a);
                s *= inv;
            }
            g_U3S[comp][t][k] = s;
        }
    }
    // symmetrized U2
    for (int item = tid; item < NCOMP * NT2; item += blockDim.x) {
        int comp = item / NT2, t = item % NT2;
        int pr = g_pair[t];
        int a = pr & 31, b = (pr >> 5) & 31;
        int kN; const float* U;
        if (comp == 0) { kN = 2; U = U2_l0; }
        else           { kN = 3; U = U2_l1 + (comp - 1) * (I_N * I_N * 3); }
        for (int k = 0; k < 4; k++) {
            float s = 0.f;
            if (k < kN) {
                s = U[(a * I_N + b) * kN + k];
                if (a != b) s += U[(b * I_N + a) * kN + k];
            }
            g_U2S[comp][t][k] = s;
        }
    }
    // U1 passthrough
    if (tid < NCOMP * I_N) {
        int comp = tid / I_N, i = tid % I_N;
        g_U1S[comp][i] = (comp == 0) ? U1_l0[i] : U1_l1[(comp - 1) * I_N + i];
    }
}

// ---------------- kernel B: fold species weights W into per-(e,c) coefficients --
__global__ void coef_kernel(const float* __restrict__ W3_l0,
                            const float* __restrict__ W2_l0,
                            const float* __restrict__ W1_l0,
                            const float* __restrict__ W3_l1,
                            const float* __restrict__ W2_l1,
                            const float* __restrict__ W1_l1) {
    int c = blockIdx.x;
    for (int idx = threadIdx.x; idx < NT * E_N * NCOMP; idx += blockDim.x) {
        int comp = idx & 3;
        int e    = (idx >> 2) % E_N;
        int t    = idx / (E_N * NCOMP);
        float v = 0.f;
        if (t < NT3) {
            if (comp == 0) {
                const float* w = W3_l0 + e * 5 * C_N + c;
#pragma unroll
                for (int k = 0; k < 5; k++) v += g_U3S[0][t][k] * w[k * C_N];
            } else {
                const float* w = W3_l1 + e * 7 * C_N + c;
#pragma unroll
                for (int k = 0; k < 7; k++) v += g_U3S[comp][t][k] * w[k * C_N];
            }
        } else if (t < NT3 + NT2) {
            int t2 = t - NT3;
            if (comp == 0) {
                const float* w = W2_l0 + e * 2 * C_N + c;
                v = g_U2S[0][t2][0] * w[0] + g_U2S[0][t2][1] * w[C_N];
            } else {
                const float* w = W2_l1 + e * 3 * C_N + c;
#pragma unroll
                for (int k = 0; k < 3; k++) v += g_U2S[comp][t2][k] * w[k * C_N];
            }
        } else {
            int i = t - NT3 - NT2;
            const float* w = (comp == 0) ? (W1_l0 + e * C_N + c)
                                         : (W1_l1 + e * C_N + c);
            v = g_U1S[comp][i] * w[0];
        }
        g_coef[c][t][e][comp] = v;
    }
}

// ---------------- kernel C: main evaluation -------------------------------------
// block = one channel c, half the batch; 154.9 KB of coefficients in SMEM.
// Batch is species-sorted so warps read coefficients as SMEM broadcasts.
__global__ void __launch_bounds__(256) main_kernel(const float* __restrict__ a_i,
                                                   float* __restrict__ out) {
    extern __shared__ float4 s_coef[];   // [NT][E_N] float4 (comp0..3)
    int c   = blockIdx.x;
    int tid = threadIdx.x;

    const float4* src = reinterpret_cast<const float4*>(&g_coef[c][0][0][0]);
#pragma unroll 4
    for (int i = tid; i < NT * E_N; i += 256) s_coef[i] = src[i];
    __syncthreads();

#pragma unroll 1
    for (int rep = 0; rep < 2; rep++) {
        int pos = blockIdx.y * 512 + rep * 256 + tid;
        int b   = g_perm[pos];
        int e   = g_species[b];
        const float4* base = s_coef + e;   // per-t offset is a compile-time imm

        const float4* xp = reinterpret_cast<const float4*>(a_i + (b * C_N + c) * I_N);
        float x[16];
        {
            float4 v0 = xp[0], v1 = xp[1], v2 = xp[2], v3 = xp[3];
            x[0]=v0.x;  x[1]=v0.y;  x[2]=v0.z;  x[3]=v0.w;
            x[4]=v1.x;  x[5]=v1.y;  x[6]=v1.z;  x[7]=v1.w;
            x[8]=v2.x;  x[9]=v2.y;  x[10]=v2.z; x[11]=v2.w;
            x[12]=v3.x; x[13]=v3.y; x[14]=v3.z; x[15]=v3.w;
        }

        float a0 = 0.f, a1 = 0.f, a2 = 0.f, a3 = 0.f;
        int t = 0;
        // cubic: Σ coef[t] * x_a x_b x_c  (a<=b<=c)
#pragma unroll
        for (int a = 0; a < I_N; a++) {
#pragma unroll
            for (int b2 = a; b2 < I_N; b2++) {
                float pab = x[a] * x[b2];
#pragma unroll
                for (int c3 = b2; c3 < I_N; c3++) {
                    float  m  = pab * x[c3];
                    float4 cf = base[t * E_N];
                    a0 = fmaf(cf.x, m, a0);
                    a1 = fmaf(cf.y, m, a1);
                    a2 = fmaf(cf.z, m, a2);
                    a3 = fmaf(cf.w, m, a3);
                    t++;
                }
            }
        }
        // quadratic
#pragma unroll
        for (int a = 0; a < I_N; a++) {
#pragma unroll
            for (int b2 = a; b2 < I_N; b2++) {
                float  m  = x[a] * x[b2];
                float4 cf = base[t * E_N];
                a0 = fmaf(cf.x, m, a0);
                a1 = fmaf(cf.y, m, a1);
                a2 = fmaf(cf.z, m, a2);
                a3 = fmaf(cf.w, m, a3);
                t++;
            }
        }
        // linear
#pragma unroll
        for (int i = 0; i < I_N; i++) {
            float4 cf = base[(NT3 + NT2 + i) * E_N];
            a0 = fmaf(cf.x, x[i], a0);
            a1 = fmaf(cf.y, x[i], a1);
            a2 = fmaf(cf.z, x[i], a2);
            a3 = fmaf(cf.w, x[i], a3);
        }

        // output layout: [b, 512] = concat(out0[b, c], out1[b, c*3+m])
        float* ob = out + b * 512;
        ob[c]               = a0;
        ob[128 + c * 3 + 0] = a1;
        ob[128 + c * 3 + 1] = a2;
        ob[128 + c * 3 + 2] = a3;
    }
}

// ---------------- launch --------------------------------------------------------
extern "C" void kernel_launch(void* const* d_in, const int* in_sizes, int n_in,
                              void* d_out, int out_size) {
    const float* a_i   = (const float*)d_in[0];
    const float* na    = (const float*)d_in[1];
    const float* U3_l0 = (const float*)d_in[2];
    const float* U2_l0 = (const float*)d_in[3];
    const float* U1_l0 = (const float*)d_in[4];
    const float* W3_l0 = (const float*)d_in[5];
    const float* W2_l0 = (const float*)d_in[6];
    const float* W1_l0 = (const float*)d_in[7];
    const float* U3_l1 = (const float*)d_in[8];
    const float* U2_l1 = (const float*)d_in[9];
    const float* U1_l1 = (const float*)d_in[10];
    const float* W3_l1 = (const float*)d_in[11];
    const float* W2_l1 = (const float*)d_in[12];
    const float* W1_l1 = (const float*)d_in[13];
    float* out = (float*)d_out;

    const int smem_bytes = NT * E_N * (int)sizeof(float4);  // 154880
    cudaFuncSetAttribute(main_kernel, cudaFuncAttributeMaxDynamicSharedMemorySize,
                         smem_bytes);

    prep_kernel<<<1, 1024>>>(na, U3_l0, U3_l1, U2_l0, U2_l1, U1_l0, U1_l1);
    coef_kernel<<<C_N, 256>>>(W3_l0, W2_l0, W1_l0, W3_l1, W2_l1, W1_l1);
    dim3 grid(C_N, 2);
    main_kernel<<<grid, 256, smem_bytes>>>(a_i, out);
}

// round 4
// speedup vs baseline: 1.5435x; 1.5435x over previous
#include <cuda_runtime.h>

#define B_N   1024
#define C_N   128
#define I_N   16
#define E_N   10
#define NT3   816           // cubic monomials i0<=i1<=i2
#define NT2   136           // quadratic monomials
#define NT    968           // 816 + 136 + 16
#define NCOMP 4             // L=0 scalar + 3 components of L=1

// ---------------- device scratch (static globals; no allocation) ----------------
__device__ int   g_species[B_N];
__device__ int   g_perm[B_N];
__device__ int   g_segstart[E_N + 1];
__device__ int   g_tri[NT3];
__device__ int   g_pair[NT2];
__device__ float g_U3S[NCOMP][NT3][8];
__device__ float g_U2S[NCOMP][NT2][4];
__device__ float g_U1S[NCOMP][I_N];
// coefficient table: [e][c][t][comp]  -> per-(e,c) slab is contiguous 15.5 KB
__device__ __align__(16) float g_coef[E_N * C_N * NT * NCOMP];  // 19.8 MB

// ---------------- kernel A: species detect + counting sort + index tables -------
__global__ void sort_kernel(const float* __restrict__ node_attrs) {
    __shared__ int s_hist[E_N];
    __shared__ int s_off[E_N];
    int tid = threadIdx.x;              // 1024 threads, 1 block
    if (tid < E_N) s_hist[tid] = 0;
    __syncthreads();

    const float* na = node_attrs + tid * E_N;
    int e = 0;
#pragma unroll
    for (int j = 0; j < E_N; j++) if (na[j] > 0.5f) e = j;
    g_species[tid] = e;
    atomicAdd(&s_hist[e], 1);
    __syncthreads();
    if (tid == 0) {
        int acc = 0;
        for (int j = 0; j < E_N; j++) {
            s_off[j] = acc; g_segstart[j] = acc; acc += s_hist[j];
        }
        g_segstart[E_N] = acc;
    }
    __syncthreads();
    int pos = atomicAdd(&s_off[e], 1);
    g_perm[pos] = tid;

    // monomial index tables (same enumeration order as main kernel loops)
    if (tid < I_N) {
        int a = tid;
        int off = 0;
        for (int ap = 0; ap < a; ap++) off += (I_N - ap) * (I_N - ap + 1) / 2;
        for (int b = a; b < I_N; b++)
            for (int c = b; c < I_N; c++)
                g_tri[off++] = a | (b << 5) | (c << 10);
        int off2 = 0;
        for (int ap = 0; ap < a; ap++) off2 += (I_N - ap);
        for (int b = a; b < I_N; b++)
            g_pair[off2++] = a | (b << 5);
    }
}

// ---------------- kernel B: grid-wide U symmetrization ---------------------------
__global__ void sym_kernel(const float* __restrict__ U3_l0,
                           const float* __restrict__ U3_l1,
                           const float* __restrict__ U2_l0,
                           const float* __restrict__ U2_l1,
                           const float* __restrict__ U1_l0,
                           const float* __restrict__ U1_l1) {
    int gtid   = blockIdx.x * blockDim.x + threadIdx.x;
    int stride = gridDim.x * blockDim.x;

    for (int item = gtid; item < NCOMP * NT3; item += stride) {
        int comp = item / NT3, t = item % NT3;
        int tr = g_tri[t];
        int a = tr & 31, b = (tr >> 5) & 31, c = (tr >> 10) & 31;
        float inv = (a == c) ? (1.f / 6.f) : ((a == b || b == c) ? 0.5f : 1.f);
        int kN; const float* U;
        if (comp == 0) { kN = 5; U = U3_l0; }
        else           { kN = 7; U = U3_l1 + (comp - 1) * (I_N * I_N * I_N * 7); }
        for (int k = 0; k < 8; k++) {
            float s = 0.f;
            if (k < kN) {
                auto at = [&](int i0, int i1, int i2) {
                    return U[((i0 * I_N + i1) * I_N + i2) * kN + k];
                };
                s = at(a,b,c) + at(a,c,b) + at(b,a,c) + at(b,c,a) + at(c,a,b) + at(c,b,a);
                s *= inv;
            }
            g_U3S[comp][t][k] = s;
        }
    }
    for (int item = gtid; item < NCOMP * NT2; item += stride) {
        int comp = item / NT2, t = item % NT2;
        int pr = g_pair[t];
        int a = pr & 31, b = (pr >> 5) & 31;
        int kN; const float* U;
        if (comp == 0) { kN = 2; U = U2_l0; }
        else           { kN = 3; U = U2_l1 + (comp - 1) * (I_N * I_N * 3); }
        for (int k = 0; k < 4; k++) {
            float s = 0.f;
            if (k < kN) {
                s = U[(a * I_N + b) * kN + k];
                if (a != b) s += U[(b * I_N + a) * kN + k];
            }
            g_U2S[comp][t][k] = s;
        }
    }
    for (int item = gtid; item < NCOMP * I_N; item += stride) {
        int comp = item / I_N, i = item % I_N;
        g_U1S[comp][i] = (comp == 0) ? U1_l0[i] : U1_l1[(comp - 1) * I_N + i];
    }
}

// ---------------- kernel C: fold species weights W into per-(e,c) coefficients --
__global__ void coef_kernel(const float* __restrict__ W3_l0,
                            const float* __restrict__ W2_l0,
                            const float* __restrict__ W1_l0,
                            const float* __restrict__ W3_l1,
                            const float* __restrict__ W2_l1,
                            const float* __restrict__ W1_l1) {
    int c = blockIdx.x;
    // idx = (e*NT + t)*4 + comp  -> consecutive idx write contiguous memory
    for (int idx = threadIdx.x; idx < E_N * NT * NCOMP; idx += blockDim.x) {
        int comp = idx & 3;
        int t    = (idx >> 2) % NT;
        int e    = idx / (NT * NCOMP);
        float v = 0.f;
        if (t < NT3) {
            if (comp == 0) {
                const float* w = W3_l0 + e * 5 * C_N + c;
#pragma unroll
                for (int k = 0; k < 5; k++) v += g_U3S[0][t][k] * w[k * C_N];
            } else {
                const float* w = W3_l1 + e * 7 * C_N + c;
#pragma unroll
                for (int k = 0; k < 7; k++) v += g_U3S[comp][t][k] * w[k * C_N];
            }
        } else if (t < NT3 + NT2) {
            int t2 = t - NT3;
            if (comp == 0) {
                const float* w = W2_l0 + e * 2 * C_N + c;
                v = g_U2S[0][t2][0] * w[0] + g_U2S[0][t2][1] * w[C_N];
            } else {
                const float* w = W2_l1 + e * 3 * C_N + c;
#pragma unroll
                for (int k = 0; k < 3; k++) v += g_U2S[comp][t2][k] * w[k * C_N];
            }
        } else {
            int i = t - NT3 - NT2;
            const float* w = (comp == 0) ? (W1_l0 + e * C_N + c)
                                         : (W1_l1 + e * C_N + c);
            v = g_U1S[comp][i] * w[0];
        }
        g_coef[((e * C_N + c) * NT + t) * NCOMP + comp] = v;
    }
}

// ---------------- kernel D: main evaluation -------------------------------------
// block = (channel c, species e). 15.5 KB SMEM -> high occupancy.
// All threads in a block share one species => coefficient LDS are broadcasts
// with immediate offsets. Scalar fmaf (f32x2 spilled catastrophically in R3).
__global__ void __launch_bounds__(128) main_kernel(const float* __restrict__ a_i,
                                                   float* __restrict__ out) {
    __shared__ __align__(16) float4 s_coef[NT];   // [t] = comp0..3
    int c   = blockIdx.x;
    int e   = blockIdx.y;
    int tid = threadIdx.x;

    const float4* src = reinterpret_cast<const float4*>(
        g_coef + (e * C_N + c) * NT * NCOMP);
#pragma unroll 4
    for (int i = tid; i < NT; i += 128) s_coef[i] = src[i];
    __syncthreads();

    int start = g_segstart[e], end = g_segstart[e + 1];

    for (int pos = start + tid; pos < end; pos += 128) {
        int b = g_perm[pos];

        const float4* xp = reinterpret_cast<const float4*>(a_i + (b * C_N + c) * I_N);
        float x[16];
        {
            float4 v0 = xp[0], v1 = xp[1], v2 = xp[2], v3 = xp[3];
            x[0]=v0.x;  x[1]=v0.y;  x[2]=v0.z;  x[3]=v0.w;
            x[4]=v1.x;  x[5]=v1.y;  x[6]=v1.z;  x[7]=v1.w;
            x[8]=v2.x;  x[9]=v2.y;  x[10]=v2.z; x[11]=v2.w;
            x[12]=v3.x; x[13]=v3.y; x[14]=v3.z; x[15]=v3.w;
        }

        float a0 = 0.f, a1 = 0.f, a2 = 0.f, a3 = 0.f;
        int t = 0, tp = 0;
#pragma unroll
        for (int a = 0; a < I_N; a++) {
#pragma unroll
            for (int b2 = a; b2 < I_N; b2++) {
                float pab = x[a] * x[b2];
                // quadratic term reuses the pair product
                {
                    float4 cq = s_coef[NT3 + tp];
                    a0 = fmaf(cq.x, pab, a0);
                    a1 = fmaf(cq.y, pab, a1);
                    a2 = fmaf(cq.z, pab, a2);
                    a3 = fmaf(cq.w, pab, a3);
                    tp++;
                }
#pragma unroll
                for (int c3 = b2; c3 < I_N; c3++) {
                    float  m  = pab * x[c3];
                    float4 cf = s_coef[t];
                    a0 = fmaf(cf.x, m, a0);
                    a1 = fmaf(cf.y, m, a1);
                    a2 = fmaf(cf.z, m, a2);
                    a3 = fmaf(cf.w, m, a3);
                    t++;
                }
            }
        }
        // linear
#pragma unroll
        for (int i = 0; i < I_N; i++) {
            float4 cl = s_coef[NT3 + NT2 + i];
            a0 = fmaf(cl.x, x[i], a0);
            a1 = fmaf(cl.y, x[i], a1);
            a2 = fmaf(cl.z, x[i], a2);
            a3 = fmaf(cl.w, x[i], a3);
        }

        // output layout: [b, 512] = concat(out0[b, c], out1[b, c*3+m])
        float* ob = out + b * 512;
        ob[c]               = a0;
        ob[128 + c * 3 + 0] = a1;
        ob[128 + c * 3 + 1] = a2;
        ob[128 + c * 3 + 2] = a3;
    }
}

// ---------------- launch --------------------------------------------------------
extern "C" void kernel_launch(void* const* d_in, const int* in_sizes, int n_in,
                              void* d_out, int out_size) {
    const float* a_i   = (const float*)d_in[0];
    const float* na    = (const float*)d_in[1];
    const float* U3_l0 = (const float*)d_in[2];
    const float* U2_l0 = (const float*)d_in[3];
    const float* U1_l0 = (const float*)d_in[4];
    const float* W3_l0 = (const float*)d_in[5];
    const float* W2_l0 = (const float*)d_in[6];
    const float* W1_l0 = (const float*)d_in[7];
    const float* U3_l1 = (const float*)d_in[8];
    const float* U2_l1 = (const float*)d_in[9];
    const float* U1_l1 = (const float*)d_in[10];
    const float* W3_l1 = (const float*)d_in[11];
    const float* W2_l1 = (const float*)d_in[12];
    const float* W1_l1 = (const float*)d_in[13];
    float* out = (float*)d_out;

    sort_kernel<<<1, 1024>>>(na);
    sym_kernel<<<32, 256>>>(U3_l0, U3_l1, U2_l0, U2_l1, U1_l0, U1_l1);
    coef_kernel<<<C_N, 256>>>(W3_l0, W2_l0, W1_l0, W3_l1, W2_l1, W1_l1);
    dim3 grid(C_N, E_N);
    main_kernel<<<grid, 128>>>(a_i, out);
}

// round 5
// speedup vs baseline: 2.0924x; 1.3556x over previous
#include <cuda_runtime.h>

#define B_N   1024
#define C_N   128
#define I_N   16
#define E_N   10
#define NT3   816           // cubic monomials i0<=i1<=i2
#define NT2   136           // quadratic monomials
#define NT    968           // 816 + 136 + 16
#define NCOMP 4             // L=0 scalar + 3 components of L=1

// ---------------- device scratch (static globals; no allocation) ----------------
__device__ int   g_perm[B_N];
__device__ int   g_segstart[E_N + 1];
__device__ __align__(32) float g_U3S[NCOMP][NT3][8];
__device__ __align__(16) float g_U2S[NCOMP][NT2][4];
__device__ float g_U1S[NCOMP][I_N];

// ---------------- kernel A: sort (block 0) + U symmetrization (blocks 1..4) ----
__global__ void prep_kernel(const float* __restrict__ node_attrs,
                            const float* __restrict__ U3_l0,
                            const float* __restrict__ U3_l1,
                            const float* __restrict__ U2_l0,
                            const float* __restrict__ U2_l1,
                            const float* __restrict__ U1_l0,
                            const float* __restrict__ U1_l1) {
    int tid = threadIdx.x;   // 1024
    if (blockIdx.x == 0) {
        __shared__ int s_hist[E_N];
        __shared__ int s_off[E_N];
        if (tid < E_N) s_hist[tid] = 0;
        __syncthreads();
        const float* na = node_attrs + tid * E_N;
        int e = 0;
#pragma unroll
        for (int j = 0; j < E_N; j++) if (na[j] > 0.5f) e = j;
        atomicAdd(&s_hist[e], 1);
        __syncthreads();
        if (tid == 0) {
            int acc = 0;
            for (int j = 0; j < E_N; j++) {
                s_off[j] = acc; g_segstart[j] = acc; acc += s_hist[j];
            }
            g_segstart[E_N] = acc;
        }
        __syncthreads();
        int pos = atomicAdd(&s_off[e], 1);
        g_perm[pos] = tid;
        return;
    }

    int gtid = (blockIdx.x - 1) * blockDim.x + tid;   // 0..4095

    // cubic symmetrization
    if (gtid < NCOMP * NT3) {
        int comp = gtid / NT3, t = gtid % NT3;
        // decode (a <= b <= c) from linear t (enumeration: a outer, b mid, c inner)
        int rem = t, a = 0;
        for (int ap = 0; ap < I_N; ap++) {
            int sz = (I_N - ap) * (I_N - ap + 1) / 2;
            if (rem < sz) { a = ap; break; }
            rem -= sz;
        }
        int b = a;
        for (int bp = a; bp < I_N; bp++) {
            int sz = I_N - bp;
            if (rem < sz) { b = bp; break; }
            rem -= sz;
        }
        int c = b + rem;
        float inv = (a == c) ? (1.f / 6.f) : ((a == b || b == c) ? 0.5f : 1.f);
        int kN; const float* U;
        if (comp == 0) { kN = 5; U = U3_l0; }
        else           { kN = 7; U = U3_l1 + (comp - 1) * (I_N * I_N * I_N * 7); }
        for (int k = 0; k < 8; k++) {
            float s = 0.f;
            if (k < kN) {
                auto at = [&](int i0, int i1, int i2) {
                    return U[((i0 * I_N + i1) * I_N + i2) * kN + k];
                };
                s = at(a,b,c) + at(a,c,b) + at(b,a,c) + at(b,c,a) + at(c,a,b) + at(c,b,a);
                s *= inv;
            }
            g_U3S[comp][t][k] = s;
        }
    }
    // quadratic symmetrization
    if (gtid < NCOMP * NT2) {
        int comp = gtid / NT2, t = gtid % NT2;
        int rem = t, a = 0;
        for (int ap = 0; ap < I_N; ap++) {
            int sz = I_N - ap;
            if (rem < sz) { a = ap; break; }
            rem -= sz;
        }
        int b = a + rem;
        int kN; const float* U;
        if (comp == 0) { kN = 2; U = U2_l0; }
        else           { kN = 3; U = U2_l1 + (comp - 1) * (I_N * I_N * 3); }
        for (int k = 0; k < 4; k++) {
            float s = 0.f;
            if (k < kN) {
                s = U[(a * I_N + b) * kN + k];
                if (a != b) s += U[(b * I_N + a) * kN + k];
            }
            g_U2S[comp][t][k] = s;
        }
    }
    // linear passthrough
    if (gtid < NCOMP * I_N) {
        int comp = gtid / I_N, i = gtid % I_N;
        g_U1S[comp][i] = (comp == 0) ? U1_l0[i] : U1_l1[(comp - 1) * I_N + i];
    }
}

// ---------------- kernel B: fused coef-fold + evaluation ------------------------
// block = (channel c, species e), 64 threads. Prologue folds W into 3872
// per-block coefficients in SMEM (reads L2-resident g_U3S). Eval: each thread
// processes TWO batch positions so every coefficient LDS.128 feeds 8 FFMA.
__global__ void __launch_bounds__(64) main_kernel(const float* __restrict__ a_i,
                                                  const float* __restrict__ W3_l0,
                                                  const float* __restrict__ W2_l0,
                                                  const float* __restrict__ W1_l0,
                                                  const float* __restrict__ W3_l1,
                                                  const float* __restrict__ W2_l1,
                                                  const float* __restrict__ W1_l1,
                                                  float* __restrict__ out) {
    __shared__ __align__(16) float4 s_coef[NT];   // 15.5 KB
    int c   = blockIdx.x;
    int e   = blockIdx.y;
    int tid = threadIdx.x;

    // ---- prologue: fold species weights into coefficients -------------------
    {
        float w30[5], w31[7], w20[2], w21[3];
#pragma unroll
        for (int k = 0; k < 5; k++) w30[k] = W3_l0[(e * 5 + k) * C_N + c];
#pragma unroll
        for (int k = 0; k < 7; k++) w31[k] = W3_l1[(e * 7 + k) * C_N + c];
#pragma unroll
        for (int k = 0; k < 2; k++) w20[k] = W2_l0[(e * 2 + k) * C_N + c];
#pragma unroll
        for (int k = 0; k < 3; k++) w21[k] = W2_l1[(e * 3 + k) * C_N + c];
        float w10 = W1_l0[e * C_N + c];
        float w11 = W1_l1[e * C_N + c];

        for (int t = tid; t < NT3; t += 64) {
            const float4* u0 = reinterpret_cast<const float4*>(&g_U3S[0][t][0]);
            float4 A0 = u0[0], A1 = u0[1];
            float c0 = A0.x*w30[0] + A0.y*w30[1] + A0.z*w30[2] + A0.w*w30[3] + A1.x*w30[4];
            const float4* u1 = reinterpret_cast<const float4*>(&g_U3S[1][t][0]);
            float4 B0 = u1[0], B1 = u1[1];
            float c1 = B0.x*w31[0] + B0.y*w31[1] + B0.z*w31[2] + B0.w*w31[3]
                     + B1.x*w31[4] + B1.y*w31[5] + B1.z*w31[6];
            const float4* u2 = reinterpret_cast<const float4*>(&g_U3S[2][t][0]);
            float4 C0 = u2[0], C1 = u2[1];
            float c2 = C0.x*w31[0] + C0.y*w31[1] + C0.z*w31[2] + C0.w*w31[3]
                     + C1.x*w31[4] + C1.y*w31[5] + C1.z*w31[6];
            const float4* u3 = reinterpret_cast<const float4*>(&g_U3S[3][t][0]);
            float4 D0 = u3[0], D1 = u3[1];
            float c3 = D0.x*w31[0] + D0.y*w31[1] + D0.z*w31[2] + D0.w*w31[3]
                     + D1.x*w31[4] + D1.y*w31[5] + D1.z*w31[6];
            s_coef[t] = make_float4(c0, c1, c2, c3);
        }
        for (int t = tid; t < NT2; t += 64) {
            const float4* q0 = reinterpret_cast<const float4*>(&g_U2S[0][t][0]);
            float4 Q0 = q0[0];
            float c0 = Q0.x*w20[0] + Q0.y*w20[1];
            const float4* q1 = reinterpret_cast<const float4*>(&g_U2S[1][t][0]);
            float4 Q1 = q1[0];
            float c1 = Q1.x*w21[0] + Q1.y*w21[1] + Q1.z*w21[2];
            const float4* q2 = reinterpret_cast<const float4*>(&g_U2S[2][t][0]);
            float4 Q2 = q2[0];
            float c2 = Q2.x*w21[0] + Q2.y*w21[1] + Q2.z*w21[2];
            const float4* q3 = reinterpret_cast<const float4*>(&g_U2S[3][t][0]);
            float4 Q3 = q3[0];
            float c3 = Q3.x*w21[0] + Q3.y*w21[1] + Q3.z*w21[2];
            s_coef[NT3 + t] = make_float4(c0, c1, c2, c3);
        }
        if (tid < I_N) {
            int i = tid;
            s_coef[NT3 + NT2 + i] = make_float4(g_U1S[0][i] * w10,
                                                g_U1S[1][i] * w11,
                                                g_U1S[2][i] * w11,
                                                g_U1S[3][i] * w11);
        }
    }
    __syncthreads();

    // ---- eval: 2 items per thread -------------------------------------------
    int start = g_segstart[e], end = g_segstart[e + 1];

    for (int p0 = start + tid; p0 < end; p0 += 128) {
        int  p1   = p0 + 64;
        bool has1 = (p1 < end);
        int  b0   = g_perm[p0];
        int  b1   = g_perm[has1 ? p1 : p0];

        float x0[16], x1[16];
        {
            const float4* xp = reinterpret_cast<const float4*>(a_i + (b0 * C_N + c) * I_N);
            float4 v0 = xp[0], v1 = xp[1], v2 = xp[2], v3 = xp[3];
            x0[0]=v0.x;  x0[1]=v0.y;  x0[2]=v0.z;  x0[3]=v0.w;
            x0[4]=v1.x;  x0[5]=v1.y;  x0[6]=v1.z;  x0[7]=v1.w;
            x0[8]=v2.x;  x0[9]=v2.y;  x0[10]=v2.z; x0[11]=v2.w;
            x0[12]=v3.x; x0[13]=v3.y; x0[14]=v3.z; x0[15]=v3.w;
        }
        {
            const float4* xp = reinterpret_cast<const float4*>(a_i + (b1 * C_N + c) * I_N);
            float4 v0 = xp[0], v1 = xp[1], v2 = xp[2], v3 = xp[3];
            x1[0]=v0.x;  x1[1]=v0.y;  x1[2]=v0.z;  x1[3]=v0.w;
            x1[4]=v1.x;  x1[5]=v1.y;  x1[6]=v1.z;  x1[7]=v1.w;
            x1[8]=v2.x;  x1[9]=v2.y;  x1[10]=v2.z; x1[11]=v2.w;
            x1[12]=v3.x; x1[13]=v3.y; x1[14]=v3.z; x1[15]=v3.w;
        }

        float a00 = 0.f, a01 = 0.f, a02 = 0.f, a03 = 0.f;
        float a10 = 0.f, a11 = 0.f, a12 = 0.f, a13 = 0.f;
        int t = 0, tp = 0;
#pragma unroll
        for (int a = 0; a < I_N; a++) {
#pragma unroll
            for (int b2 = a; b2 < I_N; b2++) {
                float pab0 = x0[a] * x0[b2];
                float pab1 = x1[a] * x1[b2];
                {   // quadratic term reuses the pair products
                    float4 cq = s_coef[NT3 + tp];
                    a00 = fmaf(cq.x, pab0, a00);  a10 = fmaf(cq.x, pab1, a10);
                    a01 = fmaf(cq.y, pab0, a01);  a11 = fmaf(cq.y, pab1, a11);
                    a02 = fmaf(cq.z, pab0, a02);  a12 = fmaf(cq.z, pab1, a12);
                    a03 = fmaf(cq.w, pab0, a03);  a13 = fmaf(cq.w, pab1, a13);
                    tp++;
                }
#pragma unroll
                for (int c3 = b2; c3 < I_N; c3++) {
                    float  m0 = pab0 * x0[c3];
                    float  m1 = pab1 * x1[c3];
                    float4 cf = s_coef[t];
                    a00 = fmaf(cf.x, m0, a00);  a10 = fmaf(cf.x, m1, a10);
                    a01 = fmaf(cf.y, m0, a01);  a11 = fmaf(cf.y, m1, a11);
                    a02 = fmaf(cf.z, m0, a02);  a12 = fmaf(cf.z, m1, a12);
                    a03 = fmaf(cf.w, m0, a03);  a13 = fmaf(cf.w, m1, a13);
                    t++;
                }
            }
        }
#pragma unroll
        for (int i = 0; i < I_N; i++) {
            float4 cl = s_coef[NT3 + NT2 + i];
            a00 = fmaf(cl.x, x0[i], a00);  a10 = fmaf(cl.x, x1[i], a10);
            a01 = fmaf(cl.y, x0[i], a01);  a11 = fmaf(cl.y, x1[i], a11);
            a02 = fmaf(cl.z, x0[i], a02);  a12 = fmaf(cl.z, x1[i], a12);
            a03 = fmaf(cl.w, x0[i], a03);  a13 = fmaf(cl.w, x1[i], a13);
        }

        // output layout: [b, 512] = concat(out0[b, c], out1[b, c*3+m])
        {
            float* ob = out + b0 * 512;
            ob[c]               = a00;
            ob[128 + c * 3 + 0] = a01;
            ob[128 + c * 3 + 1] = a02;
            ob[128 + c * 3 + 2] = a03;
        }
        if (has1) {
            float* ob = out + b1 * 512;
            ob[c]               = a10;
            ob[128 + c * 3 + 0] = a11;
            ob[128 + c * 3 + 1] = a12;
            ob[128 + c * 3 + 2] = a13;
        }
    }
}

// ---------------- launch --------------------------------------------------------
extern "C" void kernel_launch(void* const* d_in, const int* in_sizes, int n_in,
                              void* d_out, int out_size) {
    const float* a_i   = (const float*)d_in[0];
    const float* na    = (const float*)d_in[1];
    const float* U3_l0 = (const float*)d_in[2];
    const float* U2_l0 = (const float*)d_in[3];
    const float* U1_l0 = (const float*)d_in[4];
    const float* W3_l0 = (const float*)d_in[5];
    const float* W2_l0 = (const float*)d_in[6];
    const float* W1_l0 = (const float*)d_in[7];
    const float* U3_l1 = (const float*)d_in[8];
    const float* U2_l1 = (const float*)d_in[9];
    const float* U1_l1 = (const float*)d_in[10];
    const float* W3_l1 = (const float*)d_in[11];
    const float* W2_l1 = (const float*)d_in[12];
    const float* W1_l1 = (const float*)d_in[13];
    float* out = (float*)d_out;

    prep_kernel<<<5, 1024>>>(na, U3_l0, U3_l1, U2_l0, U2_l1, U1_l0, U1_l1);
    dim3 grid(C_N, E_N);
    main_kernel<<<grid, 64>>>(a_i, W3_l0, W2_l0, W1_l0, W3_l1, W2_l1, W1_l1, out);
}

// round 6
// speedup vs baseline: 2.1331x; 1.0195x over previous
#include <cuda_runtime.h>

#define B_N   1024
#define C_N   128
#define I_N   16
#define E_N   10
#define NT3   816           // cubic monomials i0<=i1<=i2
#define NT2   136           // quadratic monomials
#define NT    968           // 816 + 136 + 16
#define NCOMP 4             // L=0 scalar + 3 components of L=1

// ---------------- device scratch (static globals; no allocation) ----------------
__device__ int   g_perm[B_N];
__device__ int   g_segstart[E_N + 1];
__device__ __align__(32) float g_U3S[NCOMP][NT3][8];
__device__ __align__(16) float g_U2S[NCOMP][NT2][4];
__device__ float g_U1S[NCOMP][I_N];
// coefficient table: [e][c][t][comp] -> per-(e,c) slab contiguous 15.5 KB
__device__ __align__(16) float g_coef[E_N * C_N * NT * NCOMP];  // 19.8 MB

// ---------------- kernel A: sort (block 0) + U symmetrization (blocks 1..4) ----
__global__ void prep_kernel(const float* __restrict__ node_attrs,
                            const float* __restrict__ U3_l0,
                            const float* __restrict__ U3_l1,
                            const float* __restrict__ U2_l0,
                            const float* __restrict__ U2_l1,
                            const float* __restrict__ U1_l0,
                            const float* __restrict__ U1_l1) {
    int tid = threadIdx.x;   // 1024
    if (blockIdx.x == 0) {
        __shared__ int s_hist[E_N];
        __shared__ int s_off[E_N];
        if (tid < E_N) s_hist[tid] = 0;
        __syncthreads();
        const float* na = node_attrs + tid * E_N;
        int e = 0;
#pragma unroll
        for (int j = 0; j < E_N; j++) if (na[j] > 0.5f) e = j;
        atomicAdd(&s_hist[e], 1);
        __syncthreads();
        if (tid == 0) {
            int acc = 0;
            for (int j = 0; j < E_N; j++) {
                s_off[j] = acc; g_segstart[j] = acc; acc += s_hist[j];
            }
            g_segstart[E_N] = acc;
        }
        __syncthreads();
        int pos = atomicAdd(&s_off[e], 1);
        g_perm[pos] = tid;
        return;
    }

    int gtid = (blockIdx.x - 1) * blockDim.x + tid;   // 0..4095

    if (gtid < NCOMP * NT3) {
        int comp = gtid / NT3, t = gtid % NT3;
        int rem = t, a = 0;
        for (int ap = 0; ap < I_N; ap++) {
            int sz = (I_N - ap) * (I_N - ap + 1) / 2;
            if (rem < sz) { a = ap; break; }
            rem -= sz;
        }
        int b = a;
        for (int bp = a; bp < I_N; bp++) {
            int sz = I_N - bp;
            if (rem < sz) { b = bp; break; }
            rem -= sz;
        }
        int c = b + rem;
        float inv = (a == c) ? (1.f / 6.f) : ((a == b || b == c) ? 0.5f : 1.f);
        int kN; const float* U;
        if (comp == 0) { kN = 5; U = U3_l0; }
        else           { kN = 7; U = U3_l1 + (comp - 1) * (I_N * I_N * I_N * 7); }
        for (int k = 0; k < 8; k++) {
            float s = 0.f;
            if (k < kN) {
                auto at = [&](int i0, int i1, int i2) {
                    return U[((i0 * I_N + i1) * I_N + i2) * kN + k];
                };
                s = at(a,b,c) + at(a,c,b) + at(b,a,c) + at(b,c,a) + at(c,a,b) + at(c,b,a);
                s *= inv;
            }
            g_U3S[comp][t][k] = s;
        }
    }
    if (gtid < NCOMP * NT2) {
        int comp = gtid / NT2, t = gtid % NT2;
        int rem = t, a = 0;
        for (int ap = 0; ap < I_N; ap++) {
            int sz = I_N - ap;
            if (rem < sz) { a = ap; break; }
            rem -= sz;
        }
        int b = a + rem;
        int kN; const float* U;
        if (comp == 0) { kN = 2; U = U2_l0; }
        else           { kN = 3; U = U2_l1 + (comp - 1) * (I_N * I_N * 3); }
        for (int k = 0; k < 4; k++) {
            float s = 0.f;
            if (k < kN) {
                s = U[(a * I_N + b) * kN + k];
                if (a != b) s += U[(b * I_N + a) * kN + k];
            }
            g_U2S[comp][t][k] = s;
        }
    }
    if (gtid < NCOMP * I_N) {
        int comp = gtid / I_N, i = gtid % I_N;
        g_U1S[comp][i] = (comp == 0) ? U1_l0[i] : U1_l1[(comp - 1) * I_N + i];
    }
}

// ---------------- kernel B: coefficient fold, one block per channel -------------
// Reads g_U3S once per block (128x total, L2-resident), loops all 10 species
// with weights in SMEM; writes coalesced float4 slabs of g_coef.
__global__ void __launch_bounds__(256) coef_kernel(const float* __restrict__ W3_l0,
                                                   const float* __restrict__ W2_l0,
                                                   const float* __restrict__ W1_l0,
                                                   const float* __restrict__ W3_l1,
                                                   const float* __restrict__ W2_l1,
                                                   const float* __restrict__ W1_l1) {
    int c   = blockIdx.x;
    int tid = threadIdx.x;   // 256
    __shared__ float sw30[E_N][5], sw31[E_N][7];
    __shared__ float sw20[E_N][2], sw21[E_N][3];
    __shared__ float sw10[E_N], sw11[E_N];
    if (tid < E_N * 5) sw30[tid / 5][tid % 5] = W3_l0[tid * C_N + c];
    if (tid < E_N * 7) sw31[tid / 7][tid % 7] = W3_l1[tid * C_N + c];
    if (tid < E_N * 2) sw20[tid / 2][tid % 2] = W2_l0[tid * C_N + c];
    if (tid < E_N * 3) sw21[tid / 3][tid % 3] = W2_l1[tid * C_N + c];
    if (tid < E_N) { sw10[tid] = W1_l0[tid * C_N + c]; sw11[tid] = W1_l1[tid * C_N + c]; }
    __syncthreads();

    for (int t = tid; t < NT3; t += 256) {
        float4 A0 = reinterpret_cast<const float4*>(&g_U3S[0][t][0])[0];
        float4 A1 = reinterpret_cast<const float4*>(&g_U3S[0][t][0])[1];
        float4 B0 = reinterpret_cast<const float4*>(&g_U3S[1][t][0])[0];
        float4 B1 = reinterpret_cast<const float4*>(&g_U3S[1][t][0])[1];
        float4 C0 = reinterpret_cast<const float4*>(&g_U3S[2][t][0])[0];
        float4 C1 = reinterpret_cast<const float4*>(&g_U3S[2][t][0])[1];
        float4 D0 = reinterpret_cast<const float4*>(&g_U3S[3][t][0])[0];
        float4 D1 = reinterpret_cast<const float4*>(&g_U3S[3][t][0])[1];
#pragma unroll
        for (int e = 0; e < E_N; e++) {
            float c0 = A0.x*sw30[e][0] + A0.y*sw30[e][1] + A0.z*sw30[e][2]
                     + A0.w*sw30[e][3] + A1.x*sw30[e][4];
            float c1 = B0.x*sw31[e][0] + B0.y*sw31[e][1] + B0.z*sw31[e][2]
                     + B0.w*sw31[e][3] + B1.x*sw31[e][4] + B1.y*sw31[e][5] + B1.z*sw31[e][6];
            float c2 = C0.x*sw31[e][0] + C0.y*sw31[e][1] + C0.z*sw31[e][2]
                     + C0.w*sw31[e][3] + C1.x*sw31[e][4] + C1.y*sw31[e][5] + C1.z*sw31[e][6];
            float c3 = D0.x*sw31[e][0] + D0.y*sw31[e][1] + D0.z*sw31[e][2]
                     + D0.w*sw31[e][3] + D1.x*sw31[e][4] + D1.y*sw31[e][5] + D1.z*sw31[e][6];
            reinterpret_cast<float4*>(g_coef)[(e * C_N + c) * NT + t] =
                make_float4(c0, c1, c2, c3);
        }
    }
    for (int t = tid; t < NT2; t += 256) {
        float4 Q0 = reinterpret_cast<const float4*>(&g_U2S[0][t][0])[0];
        float4 Q1 = reinterpret_cast<const float4*>(&g_U2S[1][t][0])[0];
        float4 Q2 = reinterpret_cast<const float4*>(&g_U2S[2][t][0])[0];
        float4 Q3 = reinterpret_cast<const float4*>(&g_U2S[3][t][0])[0];
#pragma unroll
        for (int e = 0; e < E_N; e++) {
            float c0 = Q0.x*sw20[e][0] + Q0.y*sw20[e][1];
            float c1 = Q1.x*sw21[e][0] + Q1.y*sw21[e][1] + Q1.z*sw21[e][2];
            float c2 = Q2.x*sw21[e][0] + Q2.y*sw21[e][1] + Q2.z*sw21[e][2];
            float c3 = Q3.x*sw21[e][0] + Q3.y*sw21[e][1] + Q3.z*sw21[e][2];
            reinterpret_cast<float4*>(g_coef)[(e * C_N + c) * NT + NT3 + t] =
                make_float4(c0, c1, c2, c3);
        }
    }
    if (tid < I_N) {
        int i = tid;
#pragma unroll
        for (int e = 0; e < E_N; e++) {
            reinterpret_cast<float4*>(g_coef)[(e * C_N + c) * NT + NT3 + NT2 + i] =
                make_float4(g_U1S[0][i] * sw10[e], g_U1S[1][i] * sw11[e],
                            g_U1S[2][i] * sw11[e], g_U1S[3][i] * sw11[e]);
        }
    }
}

// ---------------- kernel C: evaluation ------------------------------------------
// block = (channel c, species e), 64 threads, 2 batch items per thread:
// every coefficient LDS.128 broadcast feeds 8 FFMA; 8 independent FMA chains.
__global__ void __launch_bounds__(64) main_kernel(const float* __restrict__ a_i,
                                                  float* __restrict__ out) {
    __shared__ __align__(16) float4 s_coef[NT];   // 15.5 KB
    int c   = blockIdx.x;
    int e   = blockIdx.y;
    int tid = threadIdx.x;

    const float4* src = reinterpret_cast<const float4*>(
        g_coef + (e * C_N + c) * NT * NCOMP);
#pragma unroll 4
    for (int i = tid; i < NT; i += 64) s_coef[i] = src[i];
    __syncthreads();

    int start = g_segstart[e], end = g_segstart[e + 1];

    for (int p0 = start + tid; p0 < end; p0 += 128) {
        int  p1   = p0 + 64;
        bool has1 = (p1 < end);
        int  b0   = g_perm[p0];
        int  b1   = g_perm[has1 ? p1 : p0];

        float x0[16], x1[16];
        {
            const float4* xp = reinterpret_cast<const float4*>(a_i + (b0 * C_N + c) * I_N);
            float4 v0 = xp[0], v1 = xp[1], v2 = xp[2], v3 = xp[3];
            x0[0]=v0.x;  x0[1]=v0.y;  x0[2]=v0.z;  x0[3]=v0.w;
            x0[4]=v1.x;  x0[5]=v1.y;  x0[6]=v1.z;  x0[7]=v1.w;
            x0[8]=v2.x;  x0[9]=v2.y;  x0[10]=v2.z; x0[11]=v2.w;
            x0[12]=v3.x; x0[13]=v3.y; x0[14]=v3.z; x0[15]=v3.w;
        }
        {
            const float4* xp = reinterpret_cast<const float4*>(a_i + (b1 * C_N + c) * I_N);
            float4 v0 = xp[0], v1 = xp[1], v2 = xp[2], v3 = xp[3];
            x1[0]=v0.x;  x1[1]=v0.y;  x1[2]=v0.z;  x1[3]=v0.w;
            x1[4]=v1.x;  x1[5]=v1.y;  x1[6]=v1.z;  x1[7]=v1.w;
            x1[8]=v2.x;  x1[9]=v2.y;  x1[10]=v2.z; x1[11]=v2.w;
            x1[12]=v3.x; x1[13]=v3.y; x1[14]=v3.z; x1[15]=v3.w;
        }

        float a00 = 0.f, a01 = 0.f, a02 = 0.f, a03 = 0.f;
        float a10 = 0.f, a11 = 0.f, a12 = 0.f, a13 = 0.f;
        int t = 0, tp = 0;
#pragma unroll
        for (int a = 0; a < I_N; a++) {
#pragma unroll
            for (int b2 = a; b2 < I_N; b2++) {
                float pab0 = x0[a] * x0[b2];
                float pab1 = x1[a] * x1[b2];
                {   // quadratic term reuses the pair products
                    float4 cq = s_coef[NT3 + tp];
                    a00 = fmaf(cq.x, pab0, a00);  a10 = fmaf(cq.x, pab1, a10);
                    a01 = fmaf(cq.y, pab0, a01);  a11 = fmaf(cq.y, pab1, a11);
                    a02 = fmaf(cq.z, pab0, a02);  a12 = fmaf(cq.z, pab1, a12);
                    a03 = fmaf(cq.w, pab0, a03);  a13 = fmaf(cq.w, pab1, a13);
                    tp++;
                }
#pragma unroll
                for (int c3 = b2; c3 < I_N; c3++) {
                    float  m0 = pab0 * x0[c3];
                    float  m1 = pab1 * x1[c3];
                    float4 cf = s_coef[t];
                    a00 = fmaf(cf.x, m0, a00);  a10 = fmaf(cf.x, m1, a10);
                    a01 = fmaf(cf.y, m0, a01);  a11 = fmaf(cf.y, m1, a11);
                    a02 = fmaf(cf.z, m0, a02);  a12 = fmaf(cf.z, m1, a12);
                    a03 = fmaf(cf.w, m0, a03);  a13 = fmaf(cf.w, m1, a13);
                    t++;
                }
            }
        }
#pragma unroll
        for (int i = 0; i < I_N; i++) {
            float4 cl = s_coef[NT3 + NT2 + i];
            a00 = fmaf(cl.x, x0[i], a00);  a10 = fmaf(cl.x, x1[i], a10);
            a01 = fmaf(cl.y, x0[i], a01);  a11 = fmaf(cl.y, x1[i], a11);
            a02 = fmaf(cl.z, x0[i], a02);  a12 = fmaf(cl.z, x1[i], a12);
            a03 = fmaf(cl.w, x0[i], a03);  a13 = fmaf(cl.w, x1[i], a13);
        }

        // output layout: [b, 512] = concat(out0[b, c], out1[b, c*3+m])
        {
            float* ob = out + b0 * 512;
            ob[c]               = a00;
            ob[128 + c * 3 + 0] = a01;
            ob[128 + c * 3 + 1] = a02;
            ob[128 + c * 3 + 2] = a03;
        }
        if (has1) {
            float* ob = out + b1 * 512;
            ob[c]               = a10;
            ob[128 + c * 3 + 0] = a11;
            ob[128 + c * 3 + 1] = a12;
            ob[128 + c * 3 + 2] = a13;
        }
    }
}

// ---------------- launch --------------------------------------------------------
extern "C" void kernel_launch(void* const* d_in, const int* in_sizes, int n_in,
                              void* d_out, int out_size) {
    const float* a_i   = (const float*)d_in[0];
    const float* na    = (const float*)d_in[1];
    const float* U3_l0 = (const float*)d_in[2];
    const float* U2_l0 = (const float*)d_in[3];
    const float* U1_l0 = (const float*)d_in[4];
    const float* W3_l0 = (const float*)d_in[5];
    const float* W2_l0 = (const float*)d_in[6];
    const float* W1_l0 = (const float*)d_in[7];
    const float* U3_l1 = (const float*)d_in[8];
    const float* U2_l1 = (const float*)d_in[9];
    const float* U1_l1 = (const float*)d_in[10];
    const float* W3_l1 = (const float*)d_in[11];
    const float* W2_l1 = (const float*)d_in[12];
    const float* W1_l1 = (const float*)d_in[13];
    float* out = (float*)d_out;

    prep_kernel<<<5, 1024>>>(na, U3_l0, U3_l1, U2_l0, U2_l1, U1_l0, U1_l1);
    coef_kernel<<<C_N, 256>>>(W3_l0, W2_l0, W1_l0, W3_l1, W2_l1, W1_l1);
    dim3 grid(C_N, E_N);
    main_kernel<<<grid, 64>>>(a_i, out);
}

// round 7
// speedup vs baseline: 2.6019x; 1.2198x over previous
#include <cuda_runtime.h>

#define B_N   1024
#define C_N   128
#define I_N   16
#define E_N   10
#define NT3   816           // cubic monomials i0<=i1<=i2
#define NT2   136           // quadratic monomials
#define NT    968           // 816 + 136 + 16
#define NCOMP 4             // L=0 scalar + 3 components of L=1

// ---------------- device scratch (static globals; no allocation) ----------------
__device__ int   g_perm[B_N];
__device__ int   g_segstart[E_N + 1];
__device__ __align__(32) float g_U3S[NCOMP][NT3][8];
__device__ __align__(16) float g_U2S[NCOMP][NT2][4];
__device__ float g_U1S[NCOMP][I_N];
// coefficient table: [e][c][t][comp] -> per-(e,c) slab contiguous 15.5 KB
__device__ __align__(16) float g_coef[E_N * C_N * NT * NCOMP];  // 19.8 MB

// ---------------- kernel A: sort (block 0) + U symmetrization (blocks 1..32) ---
// One thread per (comp, t, k): 26112 cubic items, 6 LDG each -> latency spread
// across ~26K threads instead of 4K.
__global__ void prep_kernel(const float* __restrict__ node_attrs,
                            const float* __restrict__ U3_l0,
                            const float* __restrict__ U3_l1,
                            const float* __restrict__ U2_l0,
                            const float* __restrict__ U2_l1,
                            const float* __restrict__ U1_l0,
                            const float* __restrict__ U1_l1) {
    int tid = threadIdx.x;   // 1024
    if (blockIdx.x == 0) {
        __shared__ int s_hist[E_N];
        __shared__ int s_off[E_N];
        if (tid < E_N) s_hist[tid] = 0;
        __syncthreads();
        const float* na = node_attrs + tid * E_N;
        int e = 0;
#pragma unroll
        for (int j = 0; j < E_N; j++) if (na[j] > 0.5f) e = j;
        atomicAdd(&s_hist[e], 1);
        __syncthreads();
        if (tid == 0) {
            int acc = 0;
            for (int j = 0; j < E_N; j++) {
                s_off[j] = acc; g_segstart[j] = acc; acc += s_hist[j];
            }
            g_segstart[E_N] = acc;
        }
        __syncthreads();
        int pos = atomicAdd(&s_off[e], 1);
        g_perm[pos] = tid;
        return;
    }

    int gtid = (blockIdx.x - 1) * blockDim.x + tid;   // 0..32767

    // cubic: one thread per (comp, t, k8)
    if (gtid < NCOMP * NT3 * 8) {
        int k    = gtid & 7;
        int t    = (gtid >> 3) % NT3;
        int comp = gtid / (NT3 * 8);
        // decode (a <= b <= c) from linear t
        int rem = t, a = 0;
        for (int ap = 0; ap < I_N; ap++) {
            int sz = (I_N - ap) * (I_N - ap + 1) / 2;
            if (rem < sz) { a = ap; break; }
            rem -= sz;
        }
        int b = a;
        for (int bp = a; bp < I_N; bp++) {
            int sz = I_N - bp;
            if (rem < sz) { b = bp; break; }
            rem -= sz;
        }
        int c = b + rem;
        float inv = (a == c) ? (1.f / 6.f) : ((a == b || b == c) ? 0.5f : 1.f);
        int kN; const float* U;
        if (comp == 0) { kN = 5; U = U3_l0; }
        else           { kN = 7; U = U3_l1 + (comp - 1) * (I_N * I_N * I_N * 7); }
        float s = 0.f;
        if (k < kN) {
            auto at = [&](int i0, int i1, int i2) {
                return U[((i0 * I_N + i1) * I_N + i2) * kN + k];
            };
            s = at(a,b,c) + at(a,c,b) + at(b,a,c) + at(b,c,a) + at(c,a,b) + at(c,b,a);
            s *= inv;
        }
        g_U3S[comp][t][k] = s;
    }
    // quadratic: one thread per (comp, t, k4)
    if (gtid < NCOMP * NT2 * 4) {
        int k    = gtid & 3;
        int t    = (gtid >> 2) % NT2;
        int comp = gtid / (NT2 * 4);
        int rem = t, a = 0;
        for (int ap = 0; ap < I_N; ap++) {
            int sz = I_N - ap;
            if (rem < sz) { a = ap; break; }
            rem -= sz;
        }
        int b = a + rem;
        int kN; const float* U;
        if (comp == 0) { kN = 2; U = U2_l0; }
        else           { kN = 3; U = U2_l1 + (comp - 1) * (I_N * I_N * 3); }
        float s = 0.f;
        if (k < kN) {
            s = U[(a * I_N + b) * kN + k];
            if (a != b) s += U[(b * I_N + a) * kN + k];
        }
        g_U2S[comp][t][k] = s;
    }
    if (gtid < NCOMP * I_N) {
        int comp = gtid / I_N, i = gtid % I_N;
        g_U1S[comp][i] = (comp == 0) ? U1_l0[i] : U1_l1[(comp - 1) * I_N + i];
    }
}

// ---------------- kernel B: coefficient fold, one block per channel -------------
__global__ void __launch_bounds__(256) coef_kernel(const float* __restrict__ W3_l0,
                                                   const float* __restrict__ W2_l0,
                                                   const float* __restrict__ W1_l0,
                                                   const float* __restrict__ W3_l1,
                                                   const float* __restrict__ W2_l1,
                                                   const float* __restrict__ W1_l1) {
    int c   = blockIdx.x;
    int tid = threadIdx.x;   // 256
    __shared__ float sw30[E_N][5], sw31[E_N][7];
    __shared__ float sw20[E_N][2], sw21[E_N][3];
    __shared__ float sw10[E_N], sw11[E_N];
    if (tid < E_N * 5) sw30[tid / 5][tid % 5] = W3_l0[tid * C_N + c];
    if (tid < E_N * 7) sw31[tid / 7][tid % 7] = W3_l1[tid * C_N + c];
    if (tid < E_N * 2) sw20[tid / 2][tid % 2] = W2_l0[tid * C_N + c];
    if (tid < E_N * 3) sw21[tid / 3][tid % 3] = W2_l1[tid * C_N + c];
    if (tid < E_N) { sw10[tid] = W1_l0[tid * C_N + c]; sw11[tid] = W1_l1[tid * C_N + c]; }
    __syncthreads();

    for (int t = tid; t < NT3; t += 256) {
        float4 A0 = reinterpret_cast<const float4*>(&g_U3S[0][t][0])[0];
        float4 A1 = reinterpret_cast<const float4*>(&g_U3S[0][t][0])[1];
        float4 B0 = reinterpret_cast<const float4*>(&g_U3S[1][t][0])[0];
        float4 B1 = reinterpret_cast<const float4*>(&g_U3S[1][t][0])[1];
        float4 C0 = reinterpret_cast<const float4*>(&g_U3S[2][t][0])[0];
        float4 C1 = reinterpret_cast<const float4*>(&g_U3S[2][t][0])[1];
        float4 D0 = reinterpret_cast<const float4*>(&g_U3S[3][t][0])[0];
        float4 D1 = reinterpret_cast<const float4*>(&g_U3S[3][t][0])[1];
#pragma unroll
        for (int e = 0; e < E_N; e++) {
            float c0 = A0.x*sw30[e][0] + A0.y*sw30[e][1] + A0.z*sw30[e][2]
                     + A0.w*sw30[e][3] + A1.x*sw30[e][4];
            float c1 = B0.x*sw31[e][0] + B0.y*sw31[e][1] + B0.z*sw31[e][2]
                     + B0.w*sw31[e][3] + B1.x*sw31[e][4] + B1.y*sw31[e][5] + B1.z*sw31[e][6];
            float c2 = C0.x*sw31[e][0] + C0.y*sw31[e][1] + C0.z*sw31[e][2]
                     + C0.w*sw31[e][3] + C1.x*sw31[e][4] + C1.y*sw31[e][5] + C1.z*sw31[e][6];
            float c3 = D0.x*sw31[e][0] + D0.y*sw31[e][1] + D0.z*sw31[e][2]
                     + D0.w*sw31[e][3] + D1.x*sw31[e][4] + D1.y*sw31[e][5] + D1.z*sw31[e][6];
            reinterpret_cast<float4*>(g_coef)[(e * C_N + c) * NT + t] =
                make_float4(c0, c1, c2, c3);
        }
    }
    for (int t = tid; t < NT2; t += 256) {
        float4 Q0 = reinterpret_cast<const float4*>(&g_U2S[0][t][0])[0];
        float4 Q1 = reinterpret_cast<const float4*>(&g_U2S[1][t][0])[0];
        float4 Q2 = reinterpret_cast<const float4*>(&g_U2S[2][t][0])[0];
        float4 Q3 = reinterpret_cast<const float4*>(&g_U2S[3][t][0])[0];
#pragma unroll
        for (int e = 0; e < E_N; e++) {
            float c0 = Q0.x*sw20[e][0] + Q0.y*sw20[e][1];
            float c1 = Q1.x*sw21[e][0] + Q1.y*sw21[e][1] + Q1.z*sw21[e][2];
            float c2 = Q2.x*sw21[e][0] + Q2.y*sw21[e][1] + Q2.z*sw21[e][2];
            float c3 = Q3.x*sw21[e][0] + Q3.y*sw21[e][1] + Q3.z*sw21[e][2];
            reinterpret_cast<float4*>(g_coef)[(e * C_N + c) * NT + NT3 + t] =
                make_float4(c0, c1, c2, c3);
        }
    }
    if (tid < I_N) {
        int i = tid;
#pragma unroll
        for (int e = 0; e < E_N; e++) {
            reinterpret_cast<float4*>(g_coef)[(e * C_N + c) * NT + NT3 + NT2 + i] =
                make_float4(g_U1S[0][i] * sw10[e], g_U1S[1][i] * sw11[e],
                            g_U1S[2][i] * sw11[e], g_U1S[3][i] * sw11[e]);
        }
    }
}

// ---------------- kernel C: evaluation ------------------------------------------
// block = (channel c, species e), 64 threads, 2 batch items per thread.
// __launch_bounds__(64, 12): cap regs ~85 -> 12 blocks/SM (24 warps) for latency
// hiding; R6 evidence showed regs=168 pinned occupancy at 15%.
__global__ void __launch_bounds__(64, 12) main_kernel(const float* __restrict__ a_i,
                                                      float* __restrict__ out) {
    __shared__ __align__(16) float4 s_coef[NT];   // 15.5 KB
    int c   = blockIdx.x;
    int e   = blockIdx.y;
    int tid = threadIdx.x;

    const float4* src = reinterpret_cast<const float4*>(
        g_coef + (e * C_N + c) * NT * NCOMP);
#pragma unroll 4
    for (int i = tid; i < NT; i += 64) s_coef[i] = src[i];
    __syncthreads();

    int start = g_segstart[e], end = g_segstart[e + 1];

    for (int p0 = start + tid; p0 < end; p0 += 128) {
        int  p1   = p0 + 64;
        bool has1 = (p1 < end);
        int  b0   = g_perm[p0];
        int  b1   = g_perm[has1 ? p1 : p0];

        float x0[16], x1[16];
        {
            const float4* xp = reinterpret_cast<const float4*>(a_i + (b0 * C_N + c) * I_N);
            float4 v0 = xp[0], v1 = xp[1], v2 = xp[2], v3 = xp[3];
            x0[0]=v0.x;  x0[1]=v0.y;  x0[2]=v0.z;  x0[3]=v0.w;
            x0[4]=v1.x;  x0[5]=v1.y;  x0[6]=v1.z;  x0[7]=v1.w;
            x0[8]=v2.x;  x0[9]=v2.y;  x0[10]=v2.z; x0[11]=v2.w;
            x0[12]=v3.x; x0[13]=v3.y; x0[14]=v3.z; x0[15]=v3.w;
        }
        {
            const float4* xp = reinterpret_cast<const float4*>(a_i + (b1 * C_N + c) * I_N);
            float4 v0 = xp[0], v1 = xp[1], v2 = xp[2], v3 = xp[3];
            x1[0]=v0.x;  x1[1]=v0.y;  x1[2]=v0.z;  x1[3]=v0.w;
            x1[4]=v1.x;  x1[5]=v1.y;  x1[6]=v1.z;  x1[7]=v1.w;
            x1[8]=v2.x;  x1[9]=v2.y;  x1[10]=v2.z; x1[11]=v2.w;
            x1[12]=v3.x; x1[13]=v3.y; x1[14]=v3.z; x1[15]=v3.w;
        }

        float a00 = 0.f, a01 = 0.f, a02 = 0.f, a03 = 0.f;
        float a10 = 0.f, a11 = 0.f, a12 = 0.f, a13 = 0.f;
        int t = 0, tp = 0;
#pragma unroll
        for (int a = 0; a < I_N; a++) {
#pragma unroll
            for (int b2 = a; b2 < I_N; b2++) {
                float pab0 = x0[a] * x0[b2];
                float pab1 = x1[a] * x1[b2];
                {   // quadratic term reuses the pair products
                    float4 cq = s_coef[NT3 + tp];
                    a00 = fmaf(cq.x, pab0, a00);  a10 = fmaf(cq.x, pab1, a10);
                    a01 = fmaf(cq.y, pab0, a01);  a11 = fmaf(cq.y, pab1, a11);
                    a02 = fmaf(cq.z, pab0, a02);  a12 = fmaf(cq.z, pab1, a12);
                    a03 = fmaf(cq.w, pab0, a03);  a13 = fmaf(cq.w, pab1, a13);
                    tp++;
                }
#pragma unroll
                for (int c3 = b2; c3 < I_N; c3++) {
                    float  m0 = pab0 * x0[c3];
                    float  m1 = pab1 * x1[c3];
                    float4 cf = s_coef[t];
                    a00 = fmaf(cf.x, m0, a00);  a10 = fmaf(cf.x, m1, a10);
                    a01 = fmaf(cf.y, m0, a01);  a11 = fmaf(cf.y, m1, a11);
                    a02 = fmaf(cf.z, m0, a02);  a12 = fmaf(cf.z, m1, a12);
                    a03 = fmaf(cf.w, m0, a03);  a13 = fmaf(cf.w, m1, a13);
                    t++;
                }
            }
        }
#pragma unroll
        for (int i = 0; i < I_N; i++) {
            float4 cl = s_coef[NT3 + NT2 + i];
            a00 = fmaf(cl.x, x0[i], a00);  a10 = fmaf(cl.x, x1[i], a10);
            a01 = fmaf(cl.y, x0[i], a01);  a11 = fmaf(cl.y, x1[i], a11);
            a02 = fmaf(cl.z, x0[i], a02);  a12 = fmaf(cl.z, x1[i], a12);
            a03 = fmaf(cl.w, x0[i], a03);  a13 = fmaf(cl.w, x1[i], a13);
        }

        // output layout: [b, 512] = concat(out0[b, c], out1[b, c*3+m])
        {
            float* ob = out + b0 * 512;
            ob[c]               = a00;
            ob[128 + c * 3 + 0] = a01;
            ob[128 + c * 3 + 1] = a02;
            ob[128 + c * 3 + 2] = a03;
        }
        if (has1) {
            float* ob = out + b1 * 512;
            ob[c]               = a10;
            ob[128 + c * 3 + 0] = a11;
            ob[128 + c * 3 + 1] = a12;
            ob[128 + c * 3 + 2] = a13;
        }
    }
}

// ---------------- launch --------------------------------------------------------
extern "C" void kernel_launch(void* const* d_in, const int* in_sizes, int n_in,
                              void* d_out, int out_size) {
    const float* a_i   = (const float*)d_in[0];
    const float* na    = (const float*)d_in[1];
    const float* U3_l0 = (const float*)d_in[2];
    const float* U2_l0 = (const float*)d_in[3];
    const float* U1_l0 = (const float*)d_in[4];
    const float* W3_l0 = (const float*)d_in[5];
    const float* W2_l0 = (const float*)d_in[6];
    const float* W1_l0 = (const float*)d_in[7];
    const float* U3_l1 = (const float*)d_in[8];
    const float* U2_l1 = (const float*)d_in[9];
    const float* U1_l1 = (const float*)d_in[10];
    const float* W3_l1 = (const float*)d_in[11];
    const float* W2_l1 = (const float*)d_in[12];
    const float* W1_l1 = (const float*)d_in[13];
    float* out = (float*)d_out;

    prep_kernel<<<33, 1024>>>(na, U3_l0, U3_l1, U2_l0, U2_l1, U1_l0, U1_l1);
    coef_kernel<<<C_N, 256>>>(W3_l0, W2_l0, W1_l0, W3_l1, W2_l1, W1_l1);
    dim3 grid(C_N, E_N);
    main_kernel<<<grid, 64>>>(a_i, out);
}

// round 8
// speedup vs baseline: 2.8398x; 1.0914x over previous
#include <cuda_runtime.h>

#define B_N   1024
#define C_N   128
#define I_N   16
#define E_N   10
#define NT3   816           // cubic monomials i0<=i1<=i2
#define NT2   136           // quadratic monomials
#define NT    968           // 816 + 136 + 16
#define NCOMP 4             // L=0 scalar + 3 components of L=1

// ---------------- device scratch (static globals; no allocation) ----------------
__device__ int   g_perm[B_N];
__device__ int   g_segstart[E_N + 1];
__device__ __align__(32) float g_U3S[NCOMP][NT3][8];
__device__ __align__(16) float g_U2S[NCOMP][NT2][4];
__device__ float g_U1S[NCOMP][I_N];
// coefficient table: [e][c][t][comp] -> per-(e,c) slab contiguous 15.5 KB
__device__ __align__(16) float g_coef[E_N * C_N * NT * NCOMP];  // 19.8 MB

// ---------------- kernel A: sort (block 0) + U symmetrization (blocks 1..32) ---
__global__ void prep_kernel(const float* __restrict__ node_attrs,
                            const float* __restrict__ U3_l0,
                            const float* __restrict__ U3_l1,
                            const float* __restrict__ U2_l0,
                            const float* __restrict__ U2_l1,
                            const float* __restrict__ U1_l0,
                            const float* __restrict__ U1_l1) {
    int tid = threadIdx.x;   // 1024
    if (blockIdx.x == 0) {
        __shared__ int s_hist[E_N];
        __shared__ int s_off[E_N];
        if (tid < E_N) s_hist[tid] = 0;
        __syncthreads();
        const float* na = node_attrs + tid * E_N;
        int e = 0;
#pragma unroll
        for (int j = 0; j < E_N; j++) if (na[j] > 0.5f) e = j;
        atomicAdd(&s_hist[e], 1);
        __syncthreads();
        if (tid == 0) {
            int acc = 0;
            for (int j = 0; j < E_N; j++) {
                s_off[j] = acc; g_segstart[j] = acc; acc += s_hist[j];
            }
            g_segstart[E_N] = acc;
        }
        __syncthreads();
        int pos = atomicAdd(&s_off[e], 1);
        g_perm[pos] = tid;
        return;
    }

    int gtid = (blockIdx.x - 1) * blockDim.x + tid;   // 0..32767

    // cubic: one thread per (comp, t, k8)
    if (gtid < NCOMP * NT3 * 8) {
        int k    = gtid & 7;
        int t    = (gtid >> 3) % NT3;
        int comp = gtid / (NT3 * 8);
        int rem = t, a = 0;
        for (int ap = 0; ap < I_N; ap++) {
            int sz = (I_N - ap) * (I_N - ap + 1) / 2;
            if (rem < sz) { a = ap; break; }
            rem -= sz;
        }
        int b = a;
        for (int bp = a; bp < I_N; bp++) {
            int sz = I_N - bp;
            if (rem < sz) { b = bp; break; }
            rem -= sz;
        }
        int c = b + rem;
        float inv = (a == c) ? (1.f / 6.f) : ((a == b || b == c) ? 0.5f : 1.f);
        int kN; const float* U;
        if (comp == 0) { kN = 5; U = U3_l0; }
        else           { kN = 7; U = U3_l1 + (comp - 1) * (I_N * I_N * I_N * 7); }
        float s = 0.f;
        if (k < kN) {
            auto at = [&](int i0, int i1, int i2) {
                return U[((i0 * I_N + i1) * I_N + i2) * kN + k];
            };
            s = at(a,b,c) + at(a,c,b) + at(b,a,c) + at(b,c,a) + at(c,a,b) + at(c,b,a);
            s *= inv;
        }
        g_U3S[comp][t][k] = s;
    }
    // quadratic: one thread per (comp, t, k4)
    if (gtid < NCOMP * NT2 * 4) {
        int k    = gtid & 3;
        int t    = (gtid >> 2) % NT2;
        int comp = gtid / (NT2 * 4);
        int rem = t, a = 0;
        for (int ap = 0; ap < I_N; ap++) {
            int sz = I_N - ap;
            if (rem < sz) { a = ap; break; }
            rem -= sz;
        }
        int b = a + rem;
        int kN; const float* U;
        if (comp == 0) { kN = 2; U = U2_l0; }
        else           { kN = 3; U = U2_l1 + (comp - 1) * (I_N * I_N * 3); }
        float s = 0.f;
        if (k < kN) {
            s = U[(a * I_N + b) * kN + k];
            if (a != b) s += U[(b * I_N + a) * kN + k];
        }
        g_U2S[comp][t][k] = s;
    }
    if (gtid < NCOMP * I_N) {
        int comp = gtid / I_N, i = gtid % I_N;
        g_U1S[comp][i] = (comp == 0) ? U1_l0[i] : U1_l1[(comp - 1) * I_N + i];
    }
}

// ---------------- kernel B: coefficient fold, one block per channel -------------
__global__ void __launch_bounds__(256) coef_kernel(const float* __restrict__ W3_l0,
                                                   const float* __restrict__ W2_l0,
                                                   const float* __restrict__ W1_l0,
                                                   const float* __restrict__ W3_l1,
                                                   const float* __restrict__ W2_l1,
                                                   const float* __restrict__ W1_l1) {
    int c   = blockIdx.x;
    int tid = threadIdx.x;   // 256
    __shared__ float sw30[E_N][5], sw31[E_N][7];
    __shared__ float sw20[E_N][2], sw21[E_N][3];
    __shared__ float sw10[E_N], sw11[E_N];
    if (tid < E_N * 5) sw30[tid / 5][tid % 5] = W3_l0[tid * C_N + c];
    if (tid < E_N * 7) sw31[tid / 7][tid % 7] = W3_l1[tid * C_N + c];
    if (tid < E_N * 2) sw20[tid / 2][tid % 2] = W2_l0[tid * C_N + c];
    if (tid < E_N * 3) sw21[tid / 3][tid % 3] = W2_l1[tid * C_N + c];
    if (tid < E_N) { sw10[tid] = W1_l0[tid * C_N + c]; sw11[tid] = W1_l1[tid * C_N + c]; }
    __syncthreads();

    for (int t = tid; t < NT3; t += 256) {
        float4 A0 = reinterpret_cast<const float4*>(&g_U3S[0][t][0])[0];
        float4 A1 = reinterpret_cast<const float4*>(&g_U3S[0][t][0])[1];
        float4 B0 = reinterpret_cast<const float4*>(&g_U3S[1][t][0])[0];
        float4 B1 = reinterpret_cast<const float4*>(&g_U3S[1][t][0])[1];
        float4 C0 = reinterpret_cast<const float4*>(&g_U3S[2][t][0])[0];
        float4 C1 = reinterpret_cast<const float4*>(&g_U3S[2][t][0])[1];
        float4 D0 = reinterpret_cast<const float4*>(&g_U3S[3][t][0])[0];
        float4 D1 = reinterpret_cast<const float4*>(&g_U3S[3][t][0])[1];
#pragma unroll
        for (int e = 0; e < E_N; e++) {
            float c0 = A0.x*sw30[e][0] + A0.y*sw30[e][1] + A0.z*sw30[e][2]
                     + A0.w*sw30[e][3] + A1.x*sw30[e][4];
            float c1 = B0.x*sw31[e][0] + B0.y*sw31[e][1] + B0.z*sw31[e][2]
                     + B0.w*sw31[e][3] + B1.x*sw31[e][4] + B1.y*sw31[e][5] + B1.z*sw31[e][6];
            float c2 = C0.x*sw31[e][0] + C0.y*sw31[e][1] + C0.z*sw31[e][2]
                     + C0.w*sw31[e][3] + C1.x*sw31[e][4] + C1.y*sw31[e][5] + C1.z*sw31[e][6];
            float c3 = D0.x*sw31[e][0] + D0.y*sw31[e][1] + D0.z*sw31[e][2]
                     + D0.w*sw31[e][3] + D1.x*sw31[e][4] + D1.y*sw31[e][5] + D1.z*sw31[e][6];
            reinterpret_cast<float4*>(g_coef)[(e * C_N + c) * NT + t] =
                make_float4(c0, c1, c2, c3);
        }
    }
    for (int t = tid; t < NT2; t += 256) {
        float4 Q0 = reinterpret_cast<const float4*>(&g_U2S[0][t][0])[0];
        float4 Q1 = reinterpret_cast<const float4*>(&g_U2S[1][t][0])[0];
        float4 Q2 = reinterpret_cast<const float4*>(&g_U2S[2][t][0])[0];
        float4 Q3 = reinterpret_cast<const float4*>(&g_U2S[3][t][0])[0];
#pragma unroll
        for (int e = 0; e < E_N; e++) {
            float c0 = Q0.x*sw20[e][0] + Q0.y*sw20[e][1];
            float c1 = Q1.x*sw21[e][0] + Q1.y*sw21[e][1] + Q1.z*sw21[e][2];
            float c2 = Q2.x*sw21[e][0] + Q2.y*sw21[e][1] + Q2.z*sw21[e][2];
            float c3 = Q3.x*sw21[e][0] + Q3.y*sw21[e][1] + Q3.z*sw21[e][2];
            reinterpret_cast<float4*>(g_coef)[(e * C_N + c) * NT + NT3 + t] =
                make_float4(c0, c1, c2, c3);
        }
    }
    if (tid < I_N) {
        int i = tid;
#pragma unroll
        for (int e = 0; e < E_N; e++) {
            reinterpret_cast<float4*>(g_coef)[(e * C_N + c) * NT + NT3 + NT2 + i] =
                make_float4(g_U1S[0][i] * sw10[e], g_U1S[1][i] * sw11[e],
                            g_U1S[2][i] * sw11[e], g_U1S[3][i] * sw11[e]);
        }
    }
}

// ---------------- kernel C: evaluation, nested Horner form ----------------------
// block = (channel c, species e), 64 threads, 2 items/thread.
// out = Sum_a x_a*( A1_a + Sum_{b>=a} x_b*( A2_ab + Sum_{c>=b} x_c*A3_abc ) )
// No monomial FMULs; A2/A1 absorbed as first-FFMA addends. -18% issue count.
__global__ void __launch_bounds__(64, 12) main_kernel(const float* __restrict__ a_i,
                                                      float* __restrict__ out) {
    __shared__ __align__(16) float4 s_coef[NT];   // 15.5 KB
    int c   = blockIdx.x;
    int e   = blockIdx.y;
    int tid = threadIdx.x;

    const float4* src = reinterpret_cast<const float4*>(
        g_coef + (e * C_N + c) * NT * NCOMP);
#pragma unroll 4
    for (int i = tid; i < NT; i += 64) s_coef[i] = src[i];
    __syncthreads();

    int start = g_segstart[e], end = g_segstart[e + 1];

    for (int p0 = start + tid; p0 < end; p0 += 128) {
        int  p1   = p0 + 64;
        bool has1 = (p1 < end);
        int  b0   = g_perm[p0];
        int  b1   = g_perm[has1 ? p1 : p0];

        float x0[16], x1[16];
        {
            const float4* xp = reinterpret_cast<const float4*>(a_i + (b0 * C_N + c) * I_N);
            float4 v0 = xp[0], v1 = xp[1], v2 = xp[2], v3 = xp[3];
            x0[0]=v0.x;  x0[1]=v0.y;  x0[2]=v0.z;  x0[3]=v0.w;
            x0[4]=v1.x;  x0[5]=v1.y;  x0[6]=v1.z;  x0[7]=v1.w;
            x0[8]=v2.x;  x0[9]=v2.y;  x0[10]=v2.z; x0[11]=v2.w;
            x0[12]=v3.x; x0[13]=v3.y; x0[14]=v3.z; x0[15]=v3.w;
        }
        {
            const float4* xp = reinterpret_cast<const float4*>(a_i + (b1 * C_N + c) * I_N);
            float4 v0 = xp[0], v1 = xp[1], v2 = xp[2], v3 = xp[3];
            x1[0]=v0.x;  x1[1]=v0.y;  x1[2]=v0.z;  x1[3]=v0.w;
            x1[4]=v1.x;  x1[5]=v1.y;  x1[6]=v1.z;  x1[7]=v1.w;
            x1[8]=v2.x;  x1[9]=v2.y;  x1[10]=v2.z; x1[11]=v2.w;
            x1[12]=v3.x; x1[13]=v3.y; x1[14]=v3.z; x1[15]=v3.w;
        }

        float o00 = 0.f, o01 = 0.f, o02 = 0.f, o03 = 0.f;
        float o10 = 0.f, o11 = 0.f, o12 = 0.f, o13 = 0.f;
        int t = 0, tp = 0;
#pragma unroll
        for (int a = 0; a < I_N; a++) {
            // t2 accumulators (per comp, per item); init deferred to first b-fold
            float t200, t201, t202, t203, t210, t211, t212, t213;
            float4 cl = s_coef[NT3 + NT2 + a];   // linear coef A1_a
#pragma unroll
            for (int b2 = a; b2 < I_N; b2++) {
                // t3 accumulators; first c-iteration absorbs quad coef A2_ab
                float4 cq = s_coef[NT3 + tp]; tp++;
                float t300, t301, t302, t303, t310, t311, t312, t313;
                {
                    float4 cf = s_coef[t]; t++;   // c3 == b2 term
                    t300 = fmaf(cf.x, x0[b2], cq.x);  t310 = fmaf(cf.x, x1[b2], cq.x);
                    t301 = fmaf(cf.y, x0[b2], cq.y);  t311 = fmaf(cf.y, x1[b2], cq.y);
                    t302 = fmaf(cf.z, x0[b2], cq.z);  t312 = fmaf(cf.z, x1[b2], cq.z);
                    t303 = fmaf(cf.w, x0[b2], cq.w);  t313 = fmaf(cf.w, x1[b2], cq.w);
                }
#pragma unroll
                for (int c3 = b2 + 1; c3 < I_N; c3++) {
                    float4 cf = s_coef[t]; t++;
                    t300 = fmaf(cf.x, x0[c3], t300);  t310 = fmaf(cf.x, x1[c3], t310);
                    t301 = fmaf(cf.y, x0[c3], t301);  t311 = fmaf(cf.y, x1[c3], t311);
                    t302 = fmaf(cf.z, x0[c3], t302);  t312 = fmaf(cf.z, x1[c3], t312);
                    t303 = fmaf(cf.w, x0[c3], t303);  t313 = fmaf(cf.w, x1[c3], t313);
                }
                if (b2 == a) {
                    // first b-fold absorbs linear coef A1_a
                    t200 = fmaf(t300, x0[b2], cl.x);  t210 = fmaf(t310, x1[b2], cl.x);
                    t201 = fmaf(t301, x0[b2], cl.y);  t211 = fmaf(t311, x1[b2], cl.y);
                    t202 = fmaf(t302, x0[b2], cl.z);  t212 = fmaf(t312, x1[b2], cl.z);
                    t203 = fmaf(t303, x0[b2], cl.w);  t213 = fmaf(t313, x1[b2], cl.w);
                } else {
                    t200 = fmaf(t300, x0[b2], t200);  t210 = fmaf(t310, x1[b2], t210);
                    t201 = fmaf(t301, x0[b2], t201);  t211 = fmaf(t311, x1[b2], t211);
                    t202 = fmaf(t302, x0[b2], t202);  t212 = fmaf(t312, x1[b2], t212);
                    t203 = fmaf(t303, x0[b2], t203);  t213 = fmaf(t313, x1[b2], t213);
                }
            }
            o00 = fmaf(t200, x0[a], o00);  o10 = fmaf(t210, x1[a], o10);
            o01 = fmaf(t201, x0[a], o01);  o11 = fmaf(t211, x1[a], o11);
            o02 = fmaf(t202, x0[a], o02);  o12 = fmaf(t212, x1[a], o12);
            o03 = fmaf(t203, x0[a], o03);  o13 = fmaf(t213, x1[a], o13);
        }

        // output layout: [b, 512] = concat(out0[b, c], out1[b, c*3+m])
        {
            float* ob = out + b0 * 512;
            ob[c]               = o00;
            ob[128 + c * 3 + 0] = o01;
            ob[128 + c * 3 + 1] = o02;
            ob[128 + c * 3 + 2] = o03;
        }
        if (has1) {
            float* ob = out + b1 * 512;
            ob[c]               = o10;
            ob[128 + c * 3 + 0] = o11;
            ob[128 + c * 3 + 1] = o12;
            ob[128 + c * 3 + 2] = o13;
        }
    }
}

// ---------------- launch --------------------------------------------------------
extern "C" void kernel_launch(void* const* d_in, const int* in_sizes, int n_in,
                              void* d_out, int out_size) {
    const float* a_i   = (const float*)d_in[0];
    const float* na    = (const float*)d_in[1];
    const float* U3_l0 = (const float*)d_in[2];
    const float* U2_l0 = (const float*)d_in[3];
    const float* U1_l0 = (const float*)d_in[4];
    const float* W3_l0 = (const float*)d_in[5];
    const float* W2_l0 = (const float*)d_in[6];
    const float* W1_l0 = (const float*)d_in[7];
    const float* U3_l1 = (const float*)d_in[8];
    const float* U2_l1 = (const float*)d_in[9];
    const float* U1_l1 = (const float*)d_in[10];
    const float* W3_l1 = (const float*)d_in[11];
    const float* W2_l1 = (const float*)d_in[12];
    const float* W1_l1 = (const float*)d_in[13];
    float* out = (float*)d_out;

    prep_kernel<<<33, 1024>>>(na, U3_l0, U3_l1, U2_l0, U2_l1, U1_l0, U1_l1);
    coef_kernel<<<C_N, 256>>>(W3_l0, W2_l0, W1_l0, W3_l1, W2_l1, W1_l1);
    dim3 grid(C_N, E_N);
    main_kernel<<<grid, 64>>>(a_i, out);
}